// round 3
// baseline (speedup 1.0000x reference)
#include <cuda_runtime.h>
#include <math.h>

// ---------------------------------------------------------------------------
// WMVLoss via binned prefix sums (O(N) instead of O(N^2) pairs):
//   scores s = sigmoid(x1-x0); loss = sum_{neg i, pos j, s_j < c_i} (c_i-s_j)^2 / N
//   with c_i = gamma + s_i.  For each negative:
//     sum = cnt*c^2 - 2c*S1 + S2   over positives with s_j < c
//   cnt/S1/S2 from per-bin prefix sums (1024 bins over (0,1)); boundary bin
//   scanned element-wise. fp32*fp32 products are exact in double -> no
//   cancellation. Bin index uses s*1024 (power-of-2 mult = exact) so the
//   bin test is consistent with the s_j < c predicate.
//
// K2 resets g_cnt after use, so state is zeroed for every call (globals are
// zero-initialized at load) -> no init kernel, 2 launches total.
// ---------------------------------------------------------------------------

#define NMAX  32768
#define NBINS 1024
#define CAP   64      // ~9 expected per bin; Poisson tail beyond 64 ~ 0

__device__ int   g_cnt[NBINS];
__device__ float g_binData[NBINS * CAP];
__device__ float g_negAll[NMAX];

__global__ void wmv_score_kernel(const float* __restrict__ x,
                                 const int* __restrict__ tgt, int n) {
    int i = blockIdx.x * blockDim.x + threadIdx.x;
    if (i >= n) return;
    float x0 = x[2 * i + 0];
    float x1 = x[2 * i + 1];
    float s = 1.0f / (1.0f + expf(x0 - x1));   // softmax[:,1] for 2 classes
    if (tgt[i] == 1) {
        int b = (int)(s * 1024.0f);
        if (b > NBINS - 1) b = NBINS - 1;      // s can round to exactly 1.0f
        int k = atomicAdd(&g_cnt[b], 1);
        if (k < CAP) g_binData[b * CAP + k] = s;
        g_negAll[i] = -1.0f;                    // marker: not a negative
    } else {
        g_negAll[i] = s;
    }
}

__global__ void __launch_bounds__(NBINS)
wmv_eval_kernel(float* __restrict__ out, int n, float gamma) {
    __shared__ int    a_c[NBINS];   // inclusive prefix of counts
    __shared__ double a_1[NBINS];   // inclusive prefix of sum(s)
    __shared__ double a_2[NBINS];   // inclusive prefix of sum(s^2)
    __shared__ int    rawc[NBINS];  // raw per-bin counts
    __shared__ double wsum[32];

    const int tid = threadIdx.x;

    // Phase 1: per-bin sums in double; reset global counter for next call.
    int c = g_cnt[tid];
    g_cnt[tid] = 0;
    if (c > CAP) c = CAP;
    double s1 = 0.0, s2 = 0.0;
    const float* bd = &g_binData[tid * CAP];
    for (int k = 0; k < c; k++) {
        double s = (double)bd[k];
        s1 += s;
        s2 += s * s;
    }
    rawc[tid] = c;
    a_c[tid] = c; a_1[tid] = s1; a_2[tid] = s2;
    __syncthreads();

    // Phase 2: inclusive Hillis-Steele scan over 1024 bins (3 arrays).
#pragma unroll
    for (int off = 1; off < NBINS; off <<= 1) {
        int vc = 0; double v1 = 0.0, v2 = 0.0;
        if (tid >= off) { vc = a_c[tid - off]; v1 = a_1[tid - off]; v2 = a_2[tid - off]; }
        __syncthreads();
        if (tid >= off) { a_c[tid] += vc; a_1[tid] += v1; a_2[tid] += v2; }
        __syncthreads();
    }

    // Phase 3: evaluate every negative.
    double acc = 0.0;
    for (int i = tid; i < n; i += NBINS) {
        float s = g_negAll[i];
        if (s < 0.0f) continue;                // positive -> skip
        float cg = gamma + s;                  // threshold, in (0.3, 1.3)
        double cd = (double)cg;
        int b = (int)(cg * 1024.0f);
        if (b > NBINS) b = NBINS;
        // full bins [0, b): exclusive prefix = inclusive[b-1]
        int    nf = (b == 0) ? 0   : a_c[b - 1];
        double S1 = (b == 0) ? 0.0 : a_1[b - 1];
        double S2 = (b == 0) ? 0.0 : a_2[b - 1];
        acc += (double)nf * cd * cd - 2.0 * cd * S1 + S2;
        // boundary bin b: exact scan
        if (b < NBINS) {
            int cb = rawc[b];
            const float* bb = &g_binData[b * CAP];
            for (int k = 0; k < cb; k++) {
                float sj = bb[k];
                if (sj < cg) {
                    double m = cd - (double)sj;
                    acc += m * m;
                }
            }
        }
    }

    // Phase 4: block reduction (double) and output.
    for (int off = 16; off > 0; off >>= 1)
        acc += __shfl_down_sync(0xFFFFFFFFu, acc, off);
    const int lane = tid & 31, wid = tid >> 5;
    if (lane == 0) wsum[wid] = acc;
    __syncthreads();
    if (wid == 0) {
        double v = (lane < NBINS / 32) ? wsum[lane] : 0.0;
        for (int off = 16; off > 0; off >>= 1)
            v += __shfl_down_sync(0xFFFFFFFFu, v, off);
        if (lane == 0) out[0] = (float)(v / (double)n);
    }
}

extern "C" void kernel_launch(void* const* d_in, const int* in_sizes, int n_in,
                              void* d_out, int out_size) {
    const float* x   = (const float*)d_in[0];   // [N,2] f32
    const int*   tgt = (const int*)d_in[1];     // [N] int32 (JAX x64 off)
    float*       out = (float*)d_out;
    const int n = in_sizes[1];

    wmv_score_kernel<<<(n + 255) / 256, 256>>>(x, tgt, n);
    wmv_eval_kernel<<<1, NBINS>>>(out, n, 0.3f);
}

// round 4
// speedup vs baseline: 7.7387x; 7.7387x over previous
#include <cuda_runtime.h>
#include <math.h>

// ---------------------------------------------------------------------------
// WMVLoss, fully fused single-block kernel, O(N), fp32-only (no FP64 --
// sm_103a DFMA rt ~18 cyc/instr made the previous version 287us).
//
//   s = sigmoid(x1-x0); loss = sum_{neg i, pos j, s_j < c_i} (c_i - s_j)^2 / N,
//   c_i = gamma + s_i.
// Per negative: cnt*c^2 - 2c*S1 + S2 over full bins below bin(c) (prefix sums,
// compensated two-float), plus exact scan of the boundary bin.
// ---------------------------------------------------------------------------

#define NBINS 1024
#define NMAX  32768
#define LOCC  16          // scores cached in registers (n=16384 / 1024 thr)

__device__ float g_posArr[NMAX];   // positives grouped by bin (rebuilt each call)

// Compensated (two-float) add: exact TwoSum + renormalize.
__device__ __forceinline__ void df_add(float& hi, float& lo, float bh, float bl) {
    float s  = hi + bh;
    float bp = s - hi;
    float e  = (hi - (s - bp)) + (bh - bp);
    e += lo + bl;
    float h2 = s + e;
    lo = e - (h2 - s);
    hi = h2;
}

__global__ void __launch_bounds__(NBINS)
wmv_fused_kernel(const float* __restrict__ x, const int* __restrict__ tgt,
                 float* __restrict__ out, int n, float gamma) {
    __shared__ int   cnt[NBINS];    // atomic counters, then scatter cursors
    __shared__ int   pref[NBINS];   // inclusive prefix of counts
    __shared__ float s1h[NBINS], s1l[NBINS];
    __shared__ float s2h[NBINS], s2l[NBINS];
    __shared__ float wsum[NBINS / 32];

    const int tid = threadIdx.x;
    const int kpt = (n + NBINS - 1) / NBINS;

    cnt[tid] = 0;
    __syncthreads();

    // ---- Phase 1: scores + bin counting (positives) ----
    float    s_loc[LOCC];
    unsigned pos_mask = 0u;
#pragma unroll
    for (int k = 0; k < LOCC; k++) {
        if (k >= kpt) break;
        int i = tid + k * NBINS;
        if (i >= n) { s_loc[k] = -1.0f; continue; }
        float x0 = x[2 * i + 0];
        float x1 = x[2 * i + 1];
        float s  = 1.0f / (1.0f + expf(x0 - x1));  // softmax[:,1], 2 classes
        s_loc[k] = s;
        if (tgt[i] == 1) {
            pos_mask |= (1u << k);
            int b = (int)(s * 1024.0f);
            if (b > NBINS - 1) b = NBINS - 1;
            atomicAdd(&cnt[b], 1);
        }
    }
    __syncthreads();

    // ---- Phase 2: inclusive int scan of counts ----
    int myc = cnt[tid];
    pref[tid] = myc;
    __syncthreads();
#pragma unroll
    for (int off = 1; off < NBINS; off <<= 1) {
        int v = (tid >= off) ? pref[tid - off] : 0;
        __syncthreads();
        pref[tid] += v;
        __syncthreads();
    }
    // cursor = exclusive prefix
    cnt[tid] = pref[tid] - myc;
    __syncthreads();

    // ---- Phase 3: scatter positives into grouped global array ----
#pragma unroll
    for (int k = 0; k < LOCC; k++) {
        if (k >= kpt) break;
        if (!((pos_mask >> k) & 1u)) continue;
        float s = s_loc[k];
        int b = (int)(s * 1024.0f);
        if (b > NBINS - 1) b = NBINS - 1;
        int p = atomicAdd(&cnt[b], 1);
        g_posArr[p] = s;
    }
    __syncthreads();   // orders smem + global writes within the block

    // ---- Phase 4: per-bin S1/S2 (fp32; <=~16 small elements per bin) ----
    {
        int beg = (tid > 0) ? pref[tid - 1] : 0;
        int end = pref[tid];
        float a1 = 0.f, a2 = 0.f;
        for (int k = beg; k < end; k++) {
            float s = g_posArr[k];
            a1 += s;
            a2 = fmaf(s, s, a2);
        }
        s1h[tid] = a1; s1l[tid] = 0.f;
        s2h[tid] = a2; s2l[tid] = 0.f;
    }
    __syncthreads();

    // ---- Phase 5: compensated (two-float) inclusive scans of S1, S2 ----
#pragma unroll
    for (int off = 1; off < NBINS; off <<= 1) {
        float v1h = 0.f, v1l = 0.f, v2h = 0.f, v2l = 0.f;
        if (tid >= off) {
            v1h = s1h[tid - off]; v1l = s1l[tid - off];
            v2h = s2h[tid - off]; v2l = s2l[tid - off];
        }
        __syncthreads();
        if (tid >= off) {
            float h = s1h[tid], l = s1l[tid];
            df_add(h, l, v1h, v1l);
            s1h[tid] = h; s1l[tid] = l;
            h = s2h[tid]; l = s2l[tid];
            df_add(h, l, v2h, v2l);
            s2h[tid] = h; s2l[tid] = l;
        }
        __syncthreads();
    }

    // ---- Phase 6: evaluate negatives (Kahan fp32 per-thread accumulator) --
    float acc = 0.f, comp = 0.f;
#pragma unroll
    for (int k = 0; k < LOCC; k++) {
        if (k >= kpt) break;
        int i = tid + k * NBINS;
        if (i >= n) break;
        if ((pos_mask >> k) & 1u) continue;   // positives don't contribute
        float s = s_loc[k];
        if (s < 0.0f) continue;               // out-of-range pad
        float cg = gamma + s;                 // threshold in (gamma, 1+gamma)
        int b  = (int)(cg * 1024.0f);
        int bb = (b < NBINS) ? b : NBINS;

        float r = 0.f;
        if (bb > 0) {
            float nf = (float)pref[bb - 1];
            float A1h = s1h[bb - 1], A1l = s1l[bb - 1];
            float A2h = s2h[bb - 1], A2l = s2l[bb - 1];
            r = fmaf(nf * cg, cg, A2h);
            r = fmaf(-2.0f * cg, A1h, r);
            r += fmaf(-2.0f * cg, A1l, A2l);
        }
        if (b < NBINS) {                      // boundary bin: exact scan
            int beg = (b > 0) ? pref[b - 1] : 0;
            int end = pref[b];
            for (int q = beg; q < end; q++) {
                float m = cg - g_posArr[q];
                if (m > 0.f) r = fmaf(m, m, r);
            }
        }
        // Kahan
        float y = r - comp;
        float t = acc + y;
        comp = (t - acc) - y;
        acc = t;
    }

    // ---- Phase 7: block reduction, output ----
    float v = acc;
    for (int off = 16; off > 0; off >>= 1)
        v += __shfl_down_sync(0xFFFFFFFFu, v, off);
    const int lane = tid & 31, wid = tid >> 5;
    if (lane == 0) wsum[wid] = v;
    __syncthreads();
    if (wid == 0) {
        float u = (lane < NBINS / 32) ? wsum[lane] : 0.f;
        for (int off = 16; off > 0; off >>= 1)
            u += __shfl_down_sync(0xFFFFFFFFu, u, off);
        if (lane == 0) out[0] = u / (float)n;
    }
}

extern "C" void kernel_launch(void* const* d_in, const int* in_sizes, int n_in,
                              void* d_out, int out_size) {
    const float* x   = (const float*)d_in[0];   // [N,2] f32
    const int*   tgt = (const int*)d_in[1];     // [N] int32 (JAX x64 off)
    float*       out = (float*)d_out;
    const int n = in_sizes[1];

    wmv_fused_kernel<<<1, NBINS>>>(x, tgt, out, n, 0.3f);
}

// round 5
// speedup vs baseline: 10.6351x; 1.3743x over previous
#include <cuda_runtime.h>
#include <math.h>

// ---------------------------------------------------------------------------
// WMVLoss, fused single-block O(N) kernel, fp32-only.
//   s = sigmoid(x1-x0); loss = sum_{neg i, pos j, s_j < c_i} (c_i-s_j)^2 / N,
//   c_i = gamma + s_i.
// Per negative: cnt*c^2 - 2c*S1 + S2 over full bins below bin(c) (compensated
// two-float prefix sums) + exact scan of the boundary bin.
//
// R5 changes vs R4 (49us kernel, barrier/latency bound):
//  - Hillis-Steele smem scans (40+ barriers) -> shuffle Kogge-Stone scans
//    (2 barriers each).
//  - compacted positives array moved from global (L2 ~234cyc) to shared
//    memory (LDS 29cyc): 88KB dynamic smem via cudaFuncSetAttribute.
// ---------------------------------------------------------------------------

#define NBINS 1024
#define NMAX  16384
#define LOCC  16
// dynamic smem: pos[NMAX] | cnt[NBINS] | pref[NBINS] | s1h,s1l,s2h,s2l[NBINS]
#define SMEM_BYTES (NMAX * 4 + NBINS * 4 * 2 + NBINS * 4 * 4)

// Compensated (two-float) add: exact TwoSum + renormalize.
__device__ __forceinline__ void df_add(float& hi, float& lo, float bh, float bl) {
    float s  = hi + bh;
    float bp = s - hi;
    float e  = (hi - (s - bp)) + (bh - bp);
    e += lo + bl;
    float h2 = s + e;
    lo = e - (h2 - s);
    hi = h2;
}

__global__ void __launch_bounds__(NBINS)
wmv_fused(const float2* __restrict__ x, const int* __restrict__ tgt,
          float* __restrict__ out, int n, float gamma) {
    extern __shared__ char sm[];
    float* pos  = (float*)sm;                              // [NMAX]
    int*   cnt  = (int*)(sm + NMAX * 4);                   // [NBINS]
    int*   pref = (int*)(sm + NMAX * 4 + NBINS * 4);       // [NBINS]
    float* s1h  = (float*)(sm + NMAX * 4 + NBINS * 8);     // [NBINS] x4
    float* s1l  = s1h + NBINS;
    float* s2h  = s1l + NBINS;
    float* s2l  = s2h + NBINS;

    __shared__ int   wtot[32];
    __shared__ float w1h[32], w1l[32], w2h[32], w2l[32];
    __shared__ float wsum[32];

    const int tid  = threadIdx.x;
    const int lane = tid & 31;
    const int wid  = tid >> 5;

    cnt[tid] = 0;
    __syncthreads();

    // ---- Phase 1: scores + bin counting ----
    float    s_loc[LOCC];
    unsigned pos_mask = 0u;
#pragma unroll
    for (int k = 0; k < LOCC; k++) {
        int i = tid + k * NBINS;
        if (i >= n) { s_loc[k] = -1.0f; continue; }
        float2 p = x[i];
        float s = 1.0f / (1.0f + expf(p.x - p.y));   // softmax[:,1], 2 classes
        s_loc[k] = s;
        if (tgt[i] == 1) {
            pos_mask |= 1u << k;
            int b = (int)(s * 1024.0f);
            if (b > NBINS - 1) b = NBINS - 1;
            atomicAdd(&cnt[b], 1);
        }
    }
    __syncthreads();

    // ---- Phase 2: int inclusive scan of counts (shuffle Kogge-Stone) ----
    int own = cnt[tid];
    int inc = own;
#pragma unroll
    for (int o = 1; o < 32; o <<= 1) {
        int t = __shfl_up_sync(0xFFFFFFFFu, inc, o);
        if (lane >= o) inc += t;
    }
    if (lane == 31) wtot[wid] = inc;
    __syncthreads();
    if (wid == 0) {
        int v = wtot[lane];
#pragma unroll
        for (int o = 1; o < 32; o <<= 1) {
            int t = __shfl_up_sync(0xFFFFFFFFu, v, o);
            if (lane >= o) v += t;
        }
        wtot[lane] = v;
    }
    __syncthreads();
    {
        int woff = (wid > 0) ? wtot[wid - 1] : 0;
        int incl = inc + woff;
        pref[tid] = incl;
        cnt[tid]  = incl - own;    // scatter cursor = exclusive prefix
    }
    __syncthreads();

    // ---- Phase 3: scatter positives into smem pos[] ----
#pragma unroll
    for (int k = 0; k < LOCC; k++) {
        if (!((pos_mask >> k) & 1u)) continue;
        float s = s_loc[k];
        int b = (int)(s * 1024.0f);
        if (b > NBINS - 1) b = NBINS - 1;
        int p = atomicAdd(&cnt[b], 1);
        pos[p] = s;
    }
    __syncthreads();

    // ---- Phase 4: per-bin S1/S2 (fp32, from smem) ----
    float a1 = 0.f, a2 = 0.f;
    {
        int beg = (tid > 0) ? pref[tid - 1] : 0;
        int end = pref[tid];
        for (int q = beg; q < end; q++) {
            float s = pos[q];
            a1 += s;
            a2 = fmaf(s, s, a2);
        }
    }

    // ---- Phase 5: compensated inclusive scans of S1,S2 (shuffles) ----
    float h1 = a1, l1 = 0.f, h2 = a2, l2 = 0.f;
#pragma unroll
    for (int o = 1; o < 32; o <<= 1) {
        float th1 = __shfl_up_sync(0xFFFFFFFFu, h1, o);
        float tl1 = __shfl_up_sync(0xFFFFFFFFu, l1, o);
        float th2 = __shfl_up_sync(0xFFFFFFFFu, h2, o);
        float tl2 = __shfl_up_sync(0xFFFFFFFFu, l2, o);
        if (lane >= o) { df_add(h1, l1, th1, tl1); df_add(h2, l2, th2, tl2); }
    }
    if (lane == 31) { w1h[wid] = h1; w1l[wid] = l1; w2h[wid] = h2; w2l[wid] = l2; }
    __syncthreads();
    if (wid == 0) {
        float vh1 = w1h[lane], vl1 = w1l[lane];
        float vh2 = w2h[lane], vl2 = w2l[lane];
#pragma unroll
        for (int o = 1; o < 32; o <<= 1) {
            float th1 = __shfl_up_sync(0xFFFFFFFFu, vh1, o);
            float tl1 = __shfl_up_sync(0xFFFFFFFFu, vl1, o);
            float th2 = __shfl_up_sync(0xFFFFFFFFu, vh2, o);
            float tl2 = __shfl_up_sync(0xFFFFFFFFu, vl2, o);
            if (lane >= o) { df_add(vh1, vl1, th1, tl1); df_add(vh2, vl2, th2, tl2); }
        }
        w1h[lane] = vh1; w1l[lane] = vl1; w2h[lane] = vh2; w2l[lane] = vl2;
    }
    __syncthreads();
    if (wid > 0) {
        df_add(h1, l1, w1h[wid - 1], w1l[wid - 1]);
        df_add(h2, l2, w2h[wid - 1], w2l[wid - 1]);
    }
    s1h[tid] = h1; s1l[tid] = l1; s2h[tid] = h2; s2l[tid] = l2;
    __syncthreads();

    // ---- Phase 6: evaluate negatives (Kahan fp32) ----
    float acc = 0.f, comp = 0.f;
#pragma unroll
    for (int k = 0; k < LOCC; k++) {
        if ((pos_mask >> k) & 1u) continue;
        float s = s_loc[k];
        if (s < 0.f) continue;                 // out-of-range pad
        float cg = gamma + s;                  // threshold in (gamma, 1+gamma)
        int b  = (int)(cg * 1024.0f);
        int bb = (b < NBINS) ? b : NBINS;
        float r = 0.f;
        if (bb > 0) {
            float nf  = (float)pref[bb - 1];
            float A1h = s1h[bb - 1], A1l = s1l[bb - 1];
            float A2h = s2h[bb - 1], A2l = s2l[bb - 1];
            r = fmaf(nf * cg, cg, A2h);
            r = fmaf(-2.0f * cg, A1h, r);
            r += fmaf(-2.0f * cg, A1l, A2l);
        }
        if (b < NBINS) {                       // boundary bin: exact scan
            int beg = (b > 0) ? pref[b - 1] : 0;
            int end = pref[b];
            for (int q = beg; q < end; q++) {
                float m = cg - pos[q];
                if (m > 0.f) r = fmaf(m, m, r);
            }
        }
        float y = r - comp;
        float t = acc + y;
        comp = (t - acc) - y;
        acc = t;
    }

    // ---- Phase 7: block reduction, output ----
    float v = acc;
    for (int o = 16; o > 0; o >>= 1) v += __shfl_down_sync(0xFFFFFFFFu, v, o);
    if (lane == 0) wsum[wid] = v;
    __syncthreads();
    if (wid == 0) {
        float u = wsum[lane];                  // exactly 32 warps
        for (int o = 16; o > 0; o >>= 1) u += __shfl_down_sync(0xFFFFFFFFu, u, o);
        if (lane == 0) out[0] = u / (float)n;
    }
}

extern "C" void kernel_launch(void* const* d_in, const int* in_sizes, int n_in,
                              void* d_out, int out_size) {
    const float2* x   = (const float2*)d_in[0];  // [N,2] f32
    const int*    tgt = (const int*)d_in[1];     // [N] int32 (JAX x64 off)
    float*        out = (float*)d_out;
    const int n = in_sizes[1];

    cudaFuncSetAttribute(wmv_fused, cudaFuncAttributeMaxDynamicSharedMemorySize,
                         SMEM_BYTES);
    wmv_fused<<<1, NBINS, SMEM_BYTES>>>(x, tgt, out, n, 0.3f);
}

// round 6
// speedup vs baseline: 14.3877x; 1.3528x over previous
#include <cuda_runtime.h>
#include <math.h>

// ---------------------------------------------------------------------------
// WMVLoss, fused single-block O(N) kernel, fp32-only, no inner loops.
//   s = sigmoid(x1-x0); loss = sum_{neg i, pos j, s_j < c_i} (c_i-s_j)^2 / N,
//   c_i = gamma + s_i.
// Per negative: cnt*c^2 - 2c*S1 + S2 over all bins strictly below bin(c).
// The partial boundary bin is OMITTED: each omitted term has margin < 2^-10
// -> margin^2 < 9.6e-7; total abs error ~1e-2 vs a sum of ~1e5-1e6 (rel
// ~1e-8, tolerance is 1e-3). This removes the scatter/grouped-array/boundary
// scans that dominated R5 (35us kernel).
// Per-bin cnt/S1/S2 built with smem atomics; prefix sums via shuffle
// Kogge-Stone with two-float compensation.
// ---------------------------------------------------------------------------

#define NBINS 1024
#define LOCC  16

// Compensated (two-float) add: exact TwoSum + renormalize.
__device__ __forceinline__ void df_add(float& hi, float& lo, float bh, float bl) {
    float s  = hi + bh;
    float bp = s - hi;
    float e  = (hi - (s - bp)) + (bh - bp);
    e += lo + bl;
    float h2 = s + e;
    lo = e - (h2 - s);
    hi = h2;
}

__global__ void __launch_bounds__(NBINS)
wmv_fused(const float2* __restrict__ x, const int* __restrict__ tgt,
          float* __restrict__ out, int n, float gamma) {
    __shared__ int   cnt[NBINS];    // per-bin count -> inclusive prefix
    __shared__ float s1a[NBINS];    // per-bin sum(s)   -> prefix hi
    __shared__ float s2a[NBINS];    // per-bin sum(s^2) -> prefix hi
    __shared__ float s1lo[NBINS];   // prefix lo parts
    __shared__ float s2lo[NBINS];
    __shared__ int   wtot[32];
    __shared__ float w1h[32], w1l[32], w2h[32], w2l[32];
    __shared__ float wsum[32];

    const int tid  = threadIdx.x;
    const int lane = tid & 31;
    const int wid  = tid >> 5;

    cnt[tid] = 0;
    s1a[tid] = 0.f;
    s2a[tid] = 0.f;
    __syncthreads();

    // ---- Phase 1: scores + per-bin cnt/S1/S2 via smem atomics ----
    float    s_loc[LOCC];
    unsigned pos_mask = 0u;
#pragma unroll
    for (int k = 0; k < LOCC; k++) {
        int i = tid + k * NBINS;
        if (i >= n) { s_loc[k] = -1.0f; continue; }
        float2 p = x[i];
        float s = 1.0f / (1.0f + __expf(p.x - p.y));  // softmax[:,1], 2 cls
        s_loc[k] = s;
        if (tgt[i] == 1) {
            pos_mask |= 1u << k;
            int b = (int)(s * 1024.0f);
            if (b > NBINS - 1) b = NBINS - 1;
            atomicAdd(&cnt[b], 1);
            atomicAdd(&s1a[b], s);
            atomicAdd(&s2a[b], s * s);
        }
    }
    __syncthreads();

    // ---- Phase 2: inclusive scans (int + two compensated float) ----
    int   own = cnt[tid];
    float h1  = s1a[tid], l1 = 0.f;
    float h2  = s2a[tid], l2 = 0.f;
    int   inc = own;
#pragma unroll
    for (int o = 1; o < 32; o <<= 1) {
        int   ti  = __shfl_up_sync(0xFFFFFFFFu, inc, o);
        float th1 = __shfl_up_sync(0xFFFFFFFFu, h1, o);
        float tl1 = __shfl_up_sync(0xFFFFFFFFu, l1, o);
        float th2 = __shfl_up_sync(0xFFFFFFFFu, h2, o);
        float tl2 = __shfl_up_sync(0xFFFFFFFFu, l2, o);
        if (lane >= o) {
            inc += ti;
            df_add(h1, l1, th1, tl1);
            df_add(h2, l2, th2, tl2);
        }
    }
    if (lane == 31) {
        wtot[wid] = inc;
        w1h[wid] = h1; w1l[wid] = l1;
        w2h[wid] = h2; w2l[wid] = l2;
    }
    __syncthreads();
    if (wid == 0) {
        int   vi  = wtot[lane];
        float vh1 = w1h[lane], vl1 = w1l[lane];
        float vh2 = w2h[lane], vl2 = w2l[lane];
#pragma unroll
        for (int o = 1; o < 32; o <<= 1) {
            int   ti  = __shfl_up_sync(0xFFFFFFFFu, vi, o);
            float th1 = __shfl_up_sync(0xFFFFFFFFu, vh1, o);
            float tl1 = __shfl_up_sync(0xFFFFFFFFu, vl1, o);
            float th2 = __shfl_up_sync(0xFFFFFFFFu, vh2, o);
            float tl2 = __shfl_up_sync(0xFFFFFFFFu, vl2, o);
            if (lane >= o) {
                vi += ti;
                df_add(vh1, vl1, th1, tl1);
                df_add(vh2, vl2, th2, tl2);
            }
        }
        wtot[lane] = vi;
        w1h[lane] = vh1; w1l[lane] = vl1;
        w2h[lane] = vh2; w2l[lane] = vl2;
    }
    __syncthreads();
    if (wid > 0) {
        inc += wtot[wid - 1];
        df_add(h1, l1, w1h[wid - 1], w1l[wid - 1]);
        df_add(h2, l2, w2h[wid - 1], w2l[wid - 1]);
    }
    cnt[tid] = inc;          // inclusive count prefix
    s1a[tid] = h1; s1lo[tid] = l1;
    s2a[tid] = h2; s2lo[tid] = l2;
    __syncthreads();

    // ---- Phase 3: evaluate negatives (no inner loops) ----
    float acc = 0.f, comp = 0.f;
#pragma unroll
    for (int k = 0; k < LOCC; k++) {
        if ((pos_mask >> k) & 1u) continue;
        float s = s_loc[k];
        if (s < 0.f) continue;                 // out-of-range pad
        float cg = gamma + s;                  // threshold in (gamma, 1+gamma)
        int b = (int)(cg * 1024.0f);
        if (b > NBINS) b = NBINS;
        if (b > 0) {
            int idx = b - 1;
            float nf  = (float)cnt[idx];
            float A1h = s1a[idx], A1l = s1lo[idx];
            float A2h = s2a[idx], A2l = s2lo[idx];
            float r = fmaf(nf * cg, cg, A2h);
            r = fmaf(-2.0f * cg, A1h, r);
            r += fmaf(-2.0f * cg, A1l, A2l);
            // Kahan accumulate
            float y = r - comp;
            float t = acc + y;
            comp = (t - acc) - y;
            acc = t;
        }
    }

    // ---- Phase 4: block reduction, output ----
    float v = acc;
    for (int o = 16; o > 0; o >>= 1) v += __shfl_down_sync(0xFFFFFFFFu, v, o);
    if (lane == 0) wsum[wid] = v;
    __syncthreads();
    if (wid == 0) {
        float u = wsum[lane];                  // exactly 32 warps
        for (int o = 16; o > 0; o >>= 1) u += __shfl_down_sync(0xFFFFFFFFu, u, o);
        if (lane == 0) out[0] = u / (float)n;
    }
}

extern "C" void kernel_launch(void* const* d_in, const int* in_sizes, int n_in,
                              void* d_out, int out_size) {
    const float2* x   = (const float2*)d_in[0];  // [N,2] f32
    const int*    tgt = (const int*)d_in[1];     // [N] int32 (JAX x64 off)
    float*        out = (float*)d_out;
    const int n = in_sizes[1];

    wmv_fused<<<1, NBINS>>>(x, tgt, out, n, 0.3f);
}

// round 7
// speedup vs baseline: 19.5548x; 1.3591x over previous
#include <cuda_runtime.h>
#include <math.h>

// ---------------------------------------------------------------------------
// WMVLoss, two-kernel O(N), fp32-only.
//   s = sigmoid(x1-x0); loss = sum_{neg i, pos j, s_j < c_i} (c_i-s_j)^2 / N,
//   c_i = gamma + s_i.  Per negative: cnt*c^2 - 2c*S1 + S2 over all bins
//   strictly below bin(c) (partial boundary bin omitted: margin < 2^-10 ->
//   term < 9.6e-7, total rel error ~1e-8).
//
// R7 change vs R6 (26us single kernel): the 24K smem ATOMS (2 cyc/lane on
// ONE SM ~= 48K cycles) were the whole kernel. K1 spreads the histogram
// atomics over 16 SMs into global bins; K2 (1 block) scans + evaluates with
// zero atomics and resets the bins for the next graph replay.
// ---------------------------------------------------------------------------

#define NBINS 1024
#define NMAX  16384
#define LOCC  16

__device__ int   g_cnt[NBINS];     // zero at load; K2 re-zeros every call
__device__ float g_s1[NBINS];
__device__ float g_s2[NBINS];
__device__ float g_neg[NMAX];      // negative scores; -1 marker for positives

// Compensated (two-float) add: exact TwoSum + renormalize.
__device__ __forceinline__ void df_add(float& hi, float& lo, float bh, float bl) {
    float s  = hi + bh;
    float bp = s - hi;
    float e  = (hi - (s - bp)) + (bh - bp);
    e += lo + bl;
    float h2 = s + e;
    lo = e - (h2 - s);
    hi = h2;
}

// ---- K1: scores + distributed global histogram ----
__global__ void __launch_bounds__(1024)
wmv_hist(const float2* __restrict__ x, const int* __restrict__ tgt, int n) {
    int i = blockIdx.x * 1024 + threadIdx.x;
    if (i >= n) return;
    float2 p = x[i];
    float s = 1.0f / (1.0f + __expf(p.x - p.y));   // softmax[:,1], 2 classes
    if (tgt[i] == 1) {
        int b = (int)(s * 1024.0f);
        if (b > NBINS - 1) b = NBINS - 1;
        atomicAdd(&g_cnt[b], 1);
        atomicAdd(&g_s1[b], s);
        atomicAdd(&g_s2[b], s * s);
        g_neg[i] = -1.0f;
    } else {
        g_neg[i] = s;
    }
}

// ---- K2: scans + closed-form eval (no atomics) ----
__global__ void __launch_bounds__(NBINS)
wmv_eval(float* __restrict__ out, int n, float gamma) {
    __shared__ int   cnt[NBINS];
    __shared__ float s1a[NBINS], s1lo[NBINS];
    __shared__ float s2a[NBINS], s2lo[NBINS];
    __shared__ int   wtot[32];
    __shared__ float w1h[32], w1l[32], w2h[32], w2l[32];
    __shared__ float wsum[32];

    const int tid  = threadIdx.x;
    const int lane = tid & 31;
    const int wid  = tid >> 5;

    // Load bins and reset globals for the next replay.
    int   own = g_cnt[tid];
    float h1  = g_s1[tid], l1 = 0.f;
    float h2  = g_s2[tid], l2 = 0.f;
    g_cnt[tid] = 0;
    g_s1[tid]  = 0.f;
    g_s2[tid]  = 0.f;

    // Inclusive scans: int (counts) + two compensated float (S1, S2).
    int inc = own;
#pragma unroll
    for (int o = 1; o < 32; o <<= 1) {
        int   ti  = __shfl_up_sync(0xFFFFFFFFu, inc, o);
        float th1 = __shfl_up_sync(0xFFFFFFFFu, h1, o);
        float tl1 = __shfl_up_sync(0xFFFFFFFFu, l1, o);
        float th2 = __shfl_up_sync(0xFFFFFFFFu, h2, o);
        float tl2 = __shfl_up_sync(0xFFFFFFFFu, l2, o);
        if (lane >= o) {
            inc += ti;
            df_add(h1, l1, th1, tl1);
            df_add(h2, l2, th2, tl2);
        }
    }
    if (lane == 31) {
        wtot[wid] = inc;
        w1h[wid] = h1; w1l[wid] = l1;
        w2h[wid] = h2; w2l[wid] = l2;
    }
    __syncthreads();
    if (wid == 0) {
        int   vi  = wtot[lane];
        float vh1 = w1h[lane], vl1 = w1l[lane];
        float vh2 = w2h[lane], vl2 = w2l[lane];
#pragma unroll
        for (int o = 1; o < 32; o <<= 1) {
            int   ti  = __shfl_up_sync(0xFFFFFFFFu, vi, o);
            float th1 = __shfl_up_sync(0xFFFFFFFFu, vh1, o);
            float tl1 = __shfl_up_sync(0xFFFFFFFFu, vl1, o);
            float th2 = __shfl_up_sync(0xFFFFFFFFu, vh2, o);
            float tl2 = __shfl_up_sync(0xFFFFFFFFu, vl2, o);
            if (lane >= o) {
                vi += ti;
                df_add(vh1, vl1, th1, tl1);
                df_add(vh2, vl2, th2, tl2);
            }
        }
        wtot[lane] = vi;
        w1h[lane] = vh1; w1l[lane] = vl1;
        w2h[lane] = vh2; w2l[lane] = vl2;
    }
    __syncthreads();
    if (wid > 0) {
        inc += wtot[wid - 1];
        df_add(h1, l1, w1h[wid - 1], w1l[wid - 1]);
        df_add(h2, l2, w2h[wid - 1], w2l[wid - 1]);
    }
    cnt[tid] = inc;
    s1a[tid] = h1; s1lo[tid] = l1;
    s2a[tid] = h2; s2lo[tid] = l2;
    __syncthreads();

    // Evaluate negatives: closed form, no inner loops.
    float acc = 0.f, comp = 0.f;
#pragma unroll
    for (int k = 0; k < LOCC; k++) {
        int i = tid + k * NBINS;
        if (i >= n) break;
        float s = g_neg[i];
        if (s < 0.f) continue;                  // positive marker
        float cg = gamma + s;                   // threshold in (gamma, 1+gamma)
        int b = (int)(cg * 1024.0f);
        if (b > NBINS) b = NBINS;
        if (b > 0) {
            int idx = b - 1;
            float nf  = (float)cnt[idx];
            float A1h = s1a[idx], A1l = s1lo[idx];
            float A2h = s2a[idx], A2l = s2lo[idx];
            float r = fmaf(nf * cg, cg, A2h);
            r = fmaf(-2.0f * cg, A1h, r);
            r += fmaf(-2.0f * cg, A1l, A2l);
            float y = r - comp;                 // Kahan
            float t = acc + y;
            comp = (t - acc) - y;
            acc = t;
        }
    }

    // Block reduction, output.
    float v = acc;
    for (int o = 16; o > 0; o >>= 1) v += __shfl_down_sync(0xFFFFFFFFu, v, o);
    if (lane == 0) wsum[wid] = v;
    __syncthreads();
    if (wid == 0) {
        float u = wsum[lane];                   // exactly 32 warps
        for (int o = 16; o > 0; o >>= 1) u += __shfl_down_sync(0xFFFFFFFFu, u, o);
        if (lane == 0) out[0] = u / (float)n;
    }
}

extern "C" void kernel_launch(void* const* d_in, const int* in_sizes, int n_in,
                              void* d_out, int out_size) {
    const float2* x   = (const float2*)d_in[0];  // [N,2] f32
    const int*    tgt = (const int*)d_in[1];     // [N] int32 (JAX x64 off)
    float*        out = (float*)d_out;
    const int n = in_sizes[1];

    wmv_hist<<<(n + 1023) / 1024, 1024>>>(x, tgt, n);
    wmv_eval<<<1, NBINS>>>(out, n, 0.3f);
}

// round 8
// speedup vs baseline: 19.7245x; 1.0087x over previous
#include <cuda_runtime.h>
#include <math.h>

// ---------------------------------------------------------------------------
// WMVLoss, SINGLE-launch O(N), fp32-only, "last block" fusion.
//   s = sigmoid(x1-x0); loss = sum_{neg i, pos j, s_j < c_i} (c_i-s_j)^2 / N,
//   c_i = gamma + s_i.  Per negative: cnt*c^2 - 2c*S1 + S2 over bins strictly
//   below bin(c) (partial boundary bin omitted: term < 2^-20, rel err ~1e-8).
//
// Phase A (16 blocks): sigmoid, global bin atomics (cnt/S1/S2), g_neg write.
// threadfence + arrival counter; the LAST block alone runs phase B:
// load+reset bins, shuffle Kogge-Stone scans (two-float compensated),
// closed-form eval (4x LDG.128 prefetch per thread), reduce, write, reset.
// All global state is restored each call -> graph-replay deterministic.
// ---------------------------------------------------------------------------

#define NBINS 1024
#define NMAX  16384
#define LOCC  16

__device__ int   g_cnt[NBINS];   // zeroed at load; last block re-zeros
__device__ float g_s1[NBINS];
__device__ float g_s2[NBINS];
__device__ float g_neg[NMAX];    // negative scores; -1 marker for positives
__device__ int   g_done;         // arrival counter; last block resets

// Compensated (two-float) add: exact TwoSum + renormalize.
__device__ __forceinline__ void df_add(float& hi, float& lo, float bh, float bl) {
    float s  = hi + bh;
    float bp = s - hi;
    float e  = (hi - (s - bp)) + (bh - bp);
    e += lo + bl;
    float h2 = s + e;
    lo = e - (h2 - s);
    hi = h2;
}

__global__ void __launch_bounds__(1024)
wmv_all(const float2* __restrict__ x, const int* __restrict__ tgt,
        float* __restrict__ out, int n, float gamma) {
    __shared__ int   cnt[NBINS];
    __shared__ float s1a[NBINS], s1lo[NBINS];
    __shared__ float s2a[NBINS], s2lo[NBINS];
    __shared__ int   wtot[32];
    __shared__ float w1h[32], w1l[32], w2h[32], w2l[32];
    __shared__ float wsum[32];
    __shared__ int   amLast;

    const int tid  = threadIdx.x;
    const int lane = tid & 31;
    const int wid  = tid >> 5;

    // ---- Phase A: scores + distributed global histogram ----
    {
        int i = blockIdx.x * 1024 + tid;
        if (i < n) {
            float2 p = x[i];
            float s = 1.0f / (1.0f + __expf(p.x - p.y));  // softmax[:,1]
            if (tgt[i] == 1) {
                int b = (int)(s * 1024.0f);
                if (b > NBINS - 1) b = NBINS - 1;
                atomicAdd(&g_cnt[b], 1);
                atomicAdd(&g_s1[b], s);
                atomicAdd(&g_s2[b], s * s);
                g_neg[i] = -1.0f;
            } else {
                g_neg[i] = s;
            }
        }
    }
    __threadfence();     // publish writes before arrival
    __syncthreads();
    if (tid == 0) {
        int t = atomicAdd(&g_done, 1);
        amLast = (t == (int)gridDim.x - 1);
    }
    __syncthreads();
    if (!amLast) return;
    __threadfence();     // order reads after observing all arrivals

    // ---- Phase B (last block only) ----
    // Load bins + reset globals for the next replay.
    int   own = g_cnt[tid];
    float h1  = g_s1[tid], l1 = 0.f;
    float h2  = g_s2[tid], l2 = 0.f;
    g_cnt[tid] = 0;
    g_s1[tid]  = 0.f;
    g_s2[tid]  = 0.f;
    if (tid == 0) g_done = 0;

    // Inclusive scans: int (counts) + two compensated float (S1, S2).
    int inc = own;
#pragma unroll
    for (int o = 1; o < 32; o <<= 1) {
        int   ti  = __shfl_up_sync(0xFFFFFFFFu, inc, o);
        float th1 = __shfl_up_sync(0xFFFFFFFFu, h1, o);
        float tl1 = __shfl_up_sync(0xFFFFFFFFu, l1, o);
        float th2 = __shfl_up_sync(0xFFFFFFFFu, h2, o);
        float tl2 = __shfl_up_sync(0xFFFFFFFFu, l2, o);
        if (lane >= o) {
            inc += ti;
            df_add(h1, l1, th1, tl1);
            df_add(h2, l2, th2, tl2);
        }
    }
    if (lane == 31) {
        wtot[wid] = inc;
        w1h[wid] = h1; w1l[wid] = l1;
        w2h[wid] = h2; w2l[wid] = l2;
    }
    __syncthreads();
    if (wid == 0) {
        int   vi  = wtot[lane];
        float vh1 = w1h[lane], vl1 = w1l[lane];
        float vh2 = w2h[lane], vl2 = w2l[lane];
#pragma unroll
        for (int o = 1; o < 32; o <<= 1) {
            int   ti  = __shfl_up_sync(0xFFFFFFFFu, vi, o);
            float th1 = __shfl_up_sync(0xFFFFFFFFu, vh1, o);
            float tl1 = __shfl_up_sync(0xFFFFFFFFu, vl1, o);
            float th2 = __shfl_up_sync(0xFFFFFFFFu, vh2, o);
            float tl2 = __shfl_up_sync(0xFFFFFFFFu, vl2, o);
            if (lane >= o) {
                vi += ti;
                df_add(vh1, vl1, th1, tl1);
                df_add(vh2, vl2, th2, tl2);
            }
        }
        wtot[lane] = vi;
        w1h[lane] = vh1; w1l[lane] = vl1;
        w2h[lane] = vh2; w2l[lane] = vl2;
    }
    __syncthreads();
    if (wid > 0) {
        inc += wtot[wid - 1];
        df_add(h1, l1, w1h[wid - 1], w1l[wid - 1]);
        df_add(h2, l2, w2h[wid - 1], w2l[wid - 1]);
    }
    cnt[tid] = inc;
    s1a[tid] = h1; s1lo[tid] = l1;
    s2a[tid] = h2; s2lo[tid] = l2;
    __syncthreads();

    // Eval: thread tid owns g_neg[16*tid .. 16*tid+15]; prefetch 4x LDG.128.
    float acc = 0.f, comp = 0.f;
    const int base = tid * LOCC;
    if (base + LOCC <= n) {
        float4 v[4];
        const float4* gp = (const float4*)(g_neg + base);
#pragma unroll
        for (int q = 0; q < 4; q++) v[q] = gp[q];   // independent, MLP=4
        const float* sv = (const float*)v;
#pragma unroll
        for (int k = 0; k < LOCC; k++) {
            float s = sv[k];
            if (s < 0.f) continue;                  // positive marker
            float cg = gamma + s;
            int b = (int)(cg * 1024.0f);
            if (b > NBINS) b = NBINS;
            if (b > 0) {
                int idx = b - 1;
                float nf  = (float)cnt[idx];
                float A1h = s1a[idx], A1l = s1lo[idx];
                float A2h = s2a[idx], A2l = s2lo[idx];
                float r = fmaf(nf * cg, cg, A2h);
                r = fmaf(-2.0f * cg, A1h, r);
                r += fmaf(-2.0f * cg, A1l, A2l);
                float y = r - comp;                 // Kahan
                float t = acc + y;
                comp = (t - acc) - y;
                acc = t;
            }
        }
    } else {
        for (int k = 0; k < LOCC; k++) {            // generic tail path
            int i = base + k;
            if (i >= n) break;
            float s = g_neg[i];
            if (s < 0.f) continue;
            float cg = gamma + s;
            int b = (int)(cg * 1024.0f);
            if (b > NBINS) b = NBINS;
            if (b > 0) {
                int idx = b - 1;
                float r = fmaf((float)cnt[idx] * cg, cg, s2a[idx]);
                r = fmaf(-2.0f * cg, s1a[idx], r);
                r += fmaf(-2.0f * cg, s1lo[idx], s2lo[idx]);
                float y = r - comp;
                float t = acc + y;
                comp = (t - acc) - y;
                acc = t;
            }
        }
    }

    // Block reduction, output.
    float v = acc;
    for (int o = 16; o > 0; o >>= 1) v += __shfl_down_sync(0xFFFFFFFFu, v, o);
    if (lane == 0) wsum[wid] = v;
    __syncthreads();
    if (wid == 0) {
        float u = wsum[lane];                       // exactly 32 warps
        for (int o = 16; o > 0; o >>= 1) u += __shfl_down_sync(0xFFFFFFFFu, u, o);
        if (lane == 0) out[0] = u / (float)n;
    }
}

extern "C" void kernel_launch(void* const* d_in, const int* in_sizes, int n_in,
                              void* d_out, int out_size) {
    const float2* x   = (const float2*)d_in[0];  // [N,2] f32
    const int*    tgt = (const int*)d_in[1];     // [N] int32 (JAX x64 off)
    float*        out = (float*)d_out;
    const int n = in_sizes[1];

    wmv_all<<<(n + 1023) / 1024, 1024>>>(x, tgt, out, n, 0.3f);
}

// round 9
// speedup vs baseline: 22.7325x; 1.1525x over previous
#include <cuda_runtime.h>
#include <math.h>

// ---------------------------------------------------------------------------
// WMVLoss, single-launch O(N), fp32-only, fully grid-parallel.
//   s = sigmoid(x1-x0); loss = sum_{neg i, pos j, s_j < c_i} (c_i-s_j)^2 / N,
//   c_i = gamma + s_i.  Per negative: cnt*c^2 - 2c*S1 + S2 over bins strictly
//   below bin(c) (partial boundary bin omitted: term < 2^-20, rel err ~1e-8).
//
// R9 vs R8 (14.8us): phase B was serial on one block and re-read all scores
// through a 64KB g_neg round trip. Now scores stay in registers; after a
// grid barrier EVERY block loads the (L2-hot) 1024-bin triple, scans it
// redundantly in parallel, evaluates its own 1024 scores, and writes one
// partial. Last-arriving block sums partials in fixed order, writes out,
// and resets all global state for the next graph replay.
// ---------------------------------------------------------------------------

#define NBINS 1024

__device__ int          g_cnt[NBINS];   // zero at load; last block re-zeros
__device__ float        g_s1[NBINS];
__device__ float        g_s2[NBINS];
__device__ float        g_part[64];     // per-block partial sums
__device__ volatile int g_bar1;         // phase-A arrival counter
__device__ int          g_bar2;         // phase-B arrival counter

// Compensated (two-float) add: exact TwoSum + renormalize.
__device__ __forceinline__ void df_add(float& hi, float& lo, float bh, float bl) {
    float s  = hi + bh;
    float bp = s - hi;
    float e  = (hi - (s - bp)) + (bh - bp);
    e += lo + bl;
    float h2 = s + e;
    lo = e - (h2 - s);
    hi = h2;
}

__global__ void __launch_bounds__(1024)
wmv_all(const float2* __restrict__ x, const int* __restrict__ tgt,
        float* __restrict__ out, int n, float gamma) {
    __shared__ int   cnt[NBINS];
    __shared__ float s1a[NBINS], s1lo[NBINS];
    __shared__ float s2a[NBINS], s2lo[NBINS];
    __shared__ int   wtot[32];
    __shared__ float w1h[32], w1l[32], w2h[32], w2l[32];
    __shared__ float wsum[32];
    __shared__ int   amLast;

    const int tid  = threadIdx.x;
    const int lane = tid & 31;
    const int wid  = tid >> 5;

    // ---- Phase A: score + distributed global histogram; keep s in regs ----
    float myS   = -1.0f;     // stays -1 for positives / out-of-range
    {
        int i = blockIdx.x * 1024 + tid;
        if (i < n) {
            float2 p = x[i];
            float s = 1.0f / (1.0f + __expf(p.x - p.y));   // softmax[:,1]
            if (tgt[i] == 1) {
                int b = (int)(s * 1024.0f);
                if (b > NBINS - 1) b = NBINS - 1;
                atomicAdd(&g_cnt[b], 1);
                atomicAdd(&g_s1[b], s);
                atomicAdd(&g_s2[b], s * s);
            } else {
                myS = s;
            }
        }
    }
    __threadfence();                 // publish histogram updates
    __syncthreads();
    if (tid == 0) {
        atomicAdd((int*)&g_bar1, 1);
        while (g_bar1 < (int)gridDim.x) { }   // spin until all blocks arrive
    }
    __syncthreads();
    __threadfence();                 // acquire: order bin reads after spin

    // ---- Phase B (all blocks): load bins, scan, evaluate own scores ----
    int   own = g_cnt[tid];
    float h1  = g_s1[tid], l1 = 0.f;
    float h2  = g_s2[tid], l2 = 0.f;

    // Inclusive scans: int (counts) + two compensated float (S1, S2).
    int inc = own;
#pragma unroll
    for (int o = 1; o < 32; o <<= 1) {
        int   ti  = __shfl_up_sync(0xFFFFFFFFu, inc, o);
        float th1 = __shfl_up_sync(0xFFFFFFFFu, h1, o);
        float tl1 = __shfl_up_sync(0xFFFFFFFFu, l1, o);
        float th2 = __shfl_up_sync(0xFFFFFFFFu, h2, o);
        float tl2 = __shfl_up_sync(0xFFFFFFFFu, l2, o);
        if (lane >= o) {
            inc += ti;
            df_add(h1, l1, th1, tl1);
            df_add(h2, l2, th2, tl2);
        }
    }
    if (lane == 31) {
        wtot[wid] = inc;
        w1h[wid] = h1; w1l[wid] = l1;
        w2h[wid] = h2; w2l[wid] = l2;
    }
    __syncthreads();
    if (wid == 0) {
        int   vi  = wtot[lane];
        float vh1 = w1h[lane], vl1 = w1l[lane];
        float vh2 = w2h[lane], vl2 = w2l[lane];
#pragma unroll
        for (int o = 1; o < 32; o <<= 1) {
            int   ti  = __shfl_up_sync(0xFFFFFFFFu, vi, o);
            float th1 = __shfl_up_sync(0xFFFFFFFFu, vh1, o);
            float tl1 = __shfl_up_sync(0xFFFFFFFFu, vl1, o);
            float th2 = __shfl_up_sync(0xFFFFFFFFu, vh2, o);
            float tl2 = __shfl_up_sync(0xFFFFFFFFu, vl2, o);
            if (lane >= o) {
                vi += ti;
                df_add(vh1, vl1, th1, tl1);
                df_add(vh2, vl2, th2, tl2);
            }
        }
        wtot[lane] = vi;
        w1h[lane] = vh1; w1l[lane] = vl1;
        w2h[lane] = vh2; w2l[lane] = vl2;
    }
    __syncthreads();
    if (wid > 0) {
        inc += wtot[wid - 1];
        df_add(h1, l1, w1h[wid - 1], w1l[wid - 1]);
        df_add(h2, l2, w2h[wid - 1], w2l[wid - 1]);
    }
    cnt[tid] = inc;
    s1a[tid] = h1; s1lo[tid] = l1;
    s2a[tid] = h2; s2lo[tid] = l2;
    __syncthreads();

    // Evaluate this thread's own (register-resident) negative score.
    float r = 0.f;
    if (myS >= 0.f) {
        float cg = gamma + myS;               // threshold in (gamma, 1+gamma)
        int b = (int)(cg * 1024.0f);
        if (b > NBINS) b = NBINS;
        if (b > 0) {
            int idx = b - 1;
            float nf  = (float)cnt[idx];
            float A1h = s1a[idx], A1l = s1lo[idx];
            float A2h = s2a[idx], A2l = s2lo[idx];
            r = fmaf(nf * cg, cg, A2h);
            r = fmaf(-2.0f * cg, A1h, r);
            r += fmaf(-2.0f * cg, A1l, A2l);
        }
    }

    // Block reduction -> per-block partial (deterministic order).
    float v = r;
    for (int o = 16; o > 0; o >>= 1) v += __shfl_down_sync(0xFFFFFFFFu, v, o);
    if (lane == 0) wsum[wid] = v;
    __syncthreads();
    if (wid == 0) {
        float u = wsum[lane];                 // exactly 32 warps
        for (int o = 16; o > 0; o >>= 1) u += __shfl_down_sync(0xFFFFFFFFu, u, o);
        if (lane == 0) g_part[blockIdx.x] = u;
    }
    __threadfence();
    __syncthreads();
    if (tid == 0) {
        int t = atomicAdd(&g_bar2, 1);
        amLast = (t == (int)gridDim.x - 1);
    }
    __syncthreads();
    if (!amLast) return;
    __threadfence();

    // ---- Last block: final sum, output, reset all global state ----
    g_cnt[tid] = 0;
    g_s1[tid]  = 0.f;
    g_s2[tid]  = 0.f;
    if (tid == 0) {
        float acc = 0.f, comp = 0.f;
        int nb = (int)gridDim.x;
        for (int b = 0; b < nb; b++) {        // fixed order -> deterministic
            float y = g_part[b] - comp;
            float t = acc + y;
            comp = (t - acc) - y;
            acc = t;
        }
        out[0] = acc / (float)n;
        g_bar1 = 0;
        g_bar2 = 0;
    }
}

extern "C" void kernel_launch(void* const* d_in, const int* in_sizes, int n_in,
                              void* d_out, int out_size) {
    const float2* x   = (const float2*)d_in[0];  // [N,2] f32
    const int*    tgt = (const int*)d_in[1];     // [N] int32 (JAX x64 off)
    float*        out = (float*)d_out;
    const int n = in_sizes[1];

    wmv_all<<<(n + 1023) / 1024, 1024>>>(x, tgt, out, n, 0.3f);
}